// round 2
// baseline (speedup 1.0000x reference)
#include <cuda_runtime.h>
#include <cstdint>

// ---------------- scratch (static device globals; no runtime allocation) ----
// votes layout: [b][n][c*16+o], b<256, n<1152, c<10 (padded slots unused)
__device__ float g_votes[256u * 1152u * 160u];   // ~180 MB
__device__ float g_vsum[256 * 160];              // sum of v over previous iters

// ---------------- constants -------------------------------------------------
#define NB      256
#define NN      1152
#define NC      10
#define NO      16
#define CO      160          // NC*16 padded to c*16+o addressing, c<10 used
#define ROW     160          // floats per (b,n) row in g_votes
#define TILE_N  32           // n's per smem tile
#define NTILES  36           // 1152/32
#define TILE_F  (TILE_N*ROW) // 5120 floats per tile
#define POSE_OFF   0
#define ACT_OFF    40960
#define COUP_OFF   43520

// ---------------- cp.async helpers -----------------------------------------
__device__ __forceinline__ void cp_async16(float* smem_dst, const float* gsrc) {
    unsigned s = (unsigned)__cvta_generic_to_shared(smem_dst);
    asm volatile("cp.async.cg.shared.global [%0], [%1], 16;\n" :: "r"(s), "l"(gsrc));
}
__device__ __forceinline__ void cp_commit() {
    asm volatile("cp.async.commit_group;\n");
}
template <int N>
__device__ __forceinline__ void cp_wait() {
    asm volatile("cp.async.wait_group %0;\n" :: "n"(N));
}

// ============================================================================
// Kernel A: votes[b,n,c,o] = sum_i W[n,c,o,i] * P[b,n,i]
// grid (1152, 8): block = (n, chunk of 32 b's). 160 threads: co4 = t%40 owns
// 4 consecutive (c*16+o) outputs (W rows in registers), bsub = t/40 strides b.
// ============================================================================
__global__ __launch_bounds__(160) void votes_kernel(
    const float* __restrict__ P, const float* __restrict__ W)
{
    const int n    = blockIdx.x;
    const int bc   = blockIdx.y;           // 32-b chunk
    const int t    = threadIdx.x;
    const int co4  = t % 40;
    const int bsub = t / 40;

    __shared__ float sp[32 * 16];          // P[bc*32 .. +31][n][0..15]
    for (int idx = t; idx < 512; idx += 160) {
        int bl = idx >> 4, i = idx & 15;
        sp[idx] = P[(size_t)(bc * 32 + bl) * (NN * 16) + (size_t)n * 16 + i];
    }

    // 4 W rows (64 floats) in registers
    float w[64];
    const float4* Wv = (const float4*)(W + ((size_t)n * CO + co4 * 4) * 16);
#pragma unroll
    for (int q = 0; q < 16; q++) {
        float4 x = Wv[q];
        w[q*4+0] = x.x; w[q*4+1] = x.y; w[q*4+2] = x.z; w[q*4+3] = x.w;
    }
    __syncthreads();

    for (int bl = bsub; bl < 32; bl += 4) {
        float p[16];
        const float4* pv = (const float4*)(sp + bl * 16);
#pragma unroll
        for (int j = 0; j < 4; j++) {
            float4 x = pv[j];
            p[j*4+0] = x.x; p[j*4+1] = x.y; p[j*4+2] = x.z; p[j*4+3] = x.w;
        }
        float a0 = 0.f, a1 = 0.f, a2 = 0.f, a3 = 0.f;
#pragma unroll
        for (int i = 0; i < 16; i++) {
            a0 = fmaf(w[i],      p[i], a0);
            a1 = fmaf(w[16 + i], p[i], a1);
            a2 = fmaf(w[32 + i], p[i], a2);
            a3 = fmaf(w[48 + i], p[i], a3);
        }
        float4 ov = make_float4(a0, a1, a2, a3);
        *(float4*)(g_votes + ((size_t)(bc * 32 + bl) * NN + n) * ROW + co4 * 4) = ov;
    }
}

// ============================================================================
// Kernel B: one fused routing pass. 1 CTA per batch b, 512 threads:
//   t = nl*16 + cl  (nl: n-slot within tile, cl: capsule lane, cl<10 active)
// PASS 0: c = 0.1 uniform (softmax of zeros). PASS 1,2: logit = dot(vsum, vote).
// PASS 2 additionally writes coupling (via smem transpose), poses, activations.
// ============================================================================
template <int PASS>
__global__ __launch_bounds__(512, 2) void route_kernel(
    const float* __restrict__ bias, float* __restrict__ out)
{
    const int b  = blockIdx.x;
    const int t  = threadIdx.x;
    const int nl = t >> 4;
    const int cl = t & 15;

    // smem: two 20KB tiles + vsum(160) + coupling stage(512)
    __shared__ float sm[2 * TILE_F + 160 + 512];
    float* tile0 = sm;
    float* tile1 = sm + TILE_F;
    float* svsum = sm + 2 * TILE_F;
    float* ccs   = sm + 2 * TILE_F + 160;

    if (PASS > 0 && t < 160) svsum[t] = g_vsum[b * 160 + t];

    const float* vb = g_votes + (size_t)b * (NN * ROW);

    // prefetch tile 0
    {
#pragma unroll
        for (int i = 0; i < 3; i++) {
            int idx = t + i * 512;
            if (idx < TILE_F / 4) cp_async16(tile0 + idx * 4, vb + idx * 4);
        }
        cp_commit();
    }

    float sacc[16];
#pragma unroll
    for (int o = 0; o < 16; o++) sacc[o] = 0.f;

    __syncthreads();   // svsum visible

    for (int k = 0; k < NTILES; k++) {
        float* cur = (k & 1) ? tile1 : tile0;
        float* nxt = (k & 1) ? tile0 : tile1;
        if (k + 1 < NTILES) {
            const float* src = vb + (size_t)(k + 1) * TILE_F;
#pragma unroll
            for (int i = 0; i < 3; i++) {
                int idx = t + i * 512;
                if (idx < TILE_F / 4) cp_async16(nxt + idx * 4, src + idx * 4);
            }
            cp_commit();
            cp_wait<1>();
        } else {
            cp_wait<0>();
        }
        __syncthreads();

        // ---- process one n per thread-group of 16 lanes ----
        float vv[16];
        if (cl < 10) {
            const float4* rv = (const float4*)(cur + nl * ROW + cl * 16);
#pragma unroll
            for (int j = 0; j < 4; j++) {
                float4 x = rv[j];
                vv[j*4+0] = x.x; vv[j*4+1] = x.y; vv[j*4+2] = x.z; vv[j*4+3] = x.w;
            }
        } else {
#pragma unroll
            for (int o = 0; o < 16; o++) vv[o] = 0.f;
        }

        float cc;
        if (PASS == 0) {
            cc = 0.1f;
        } else {
            float lg;
            if (cl < 10) {
                lg = 0.f;
                const float4* sv = (const float4*)(svsum + cl * 16);
#pragma unroll
                for (int j = 0; j < 4; j++) {
                    float4 x = sv[j];
                    lg = fmaf(x.x, vv[j*4+0], lg);
                    lg = fmaf(x.y, vv[j*4+1], lg);
                    lg = fmaf(x.z, vv[j*4+2], lg);
                    lg = fmaf(x.w, vv[j*4+3], lg);
                }
            } else {
                lg = -1e30f;
            }
            float mx = lg;
#pragma unroll
            for (int m = 1; m < 16; m <<= 1)
                mx = fmaxf(mx, __shfl_xor_sync(0xFFFFFFFFu, mx, m, 16));
            float e = (cl < 10) ? __expf(lg - mx) : 0.f;
            float den = e;
#pragma unroll
            for (int m = 1; m < 16; m <<= 1)
                den += __shfl_xor_sync(0xFFFFFFFFu, den, m, 16);
            cc = e / den;
        }

        if (cl < 10) {
#pragma unroll
            for (int o = 0; o < 16; o++) sacc[o] = fmaf(cc, vv[o], sacc[o]);
        }

        if (PASS == 2) {
            if (cl < 10) ccs[nl * 16 + cl] = cc;
            __syncthreads();
            // coalesced coupling write: out[b][c][n], 32 consecutive n per c
            if (t < 320) {
                int c2 = t / 32, nn = t % 32;
                out[COUP_OFF + (size_t)b * (NC * NN) + (size_t)c2 * NN + k * TILE_N + nn] =
                    ccs[nn * 16 + c2];
            }
        }
        __syncthreads();
    }

    // ---- cross-slot reduction of s, squash, outputs ----
    float* sred = sm;   // 512*16 = 8192 floats, reuses tile region (done)
#pragma unroll
    for (int j = 0; j < 4; j++) {
        float4 x = make_float4(sacc[j*4], sacc[j*4+1], sacc[j*4+2], sacc[j*4+3]);
        *(float4*)(sred + t * 16 + j * 4) = x;
    }
    __syncthreads();

    if (t < 160) {
        const int c = t >> 4, o = t & 15;
        float s = bias[t];
#pragma unroll 8
        for (int nl2 = 0; nl2 < 32; nl2++)
            s += sred[(nl2 * 16 + c) * 16 + o];

        float sq = s * s;
#pragma unroll
        for (int m = 1; m < 16; m <<= 1)
            sq += __shfl_xor_sync(0xFFFFFFFFu, sq, m, 16);

        float norm = sqrtf(sq + 1e-8f);
        float vout = sq / (1.0f + sq) * (s / norm);

        if (PASS < 2) {
            float prev = (PASS == 0) ? 0.f : svsum[t];
            g_vsum[b * 160 + t] = prev + vout;
        } else {
            out[POSE_OFF + (size_t)b * 160 + t] = vout;
            float vsq = vout * vout;
#pragma unroll
            for (int m = 1; m < 16; m <<= 1)
                vsq += __shfl_xor_sync(0xFFFFFFFFu, vsq, m, 16);
            if (o == 0) out[ACT_OFF + b * NC + c] = sqrtf(vsq + 1e-8f);
        }
    }
}

// ============================================================================
extern "C" void kernel_launch(void* const* d_in, const int* in_sizes, int n_in,
                              void* d_out, int out_size)
{
    const float* P    = (const float*)d_in[0];  // (256,32,6,6,16,1)
    // d_in[1] = input_caps_activations — unused by the reference computation
    const float* W    = (const float*)d_in[2];  // (32,6,6,10,16,16)
    const float* bias = (const float*)d_in[3];  // (10,1,1,16,1)
    float* out = (float*)d_out;

    votes_kernel<<<dim3(NN, 8), 160>>>(P, W);
    route_kernel<0><<<NB, 512>>>(bias, out);
    route_kernel<1><<<NB, 512>>>(bias, out);
    route_kernel<2><<<NB, 512>>>(bias, out);
}

// round 3
// speedup vs baseline: 1.1616x; 1.1616x over previous
#include <cuda_runtime.h>
#include <cuda_fp16.h>
#include <cstdint>

// ---------------- scratch (static device globals) ---------------------------
__device__ __half g_votes[256u * 1152u * 160u];  // fp16 votes, ~94 MB
__device__ float  g_vsum[256 * 160];             // sum of v over prev iters
__device__ float  g_s[3][256 * 160];             // per-pass s partials (atomic)

// ---------------- constants -------------------------------------------------
#define NB      256
#define NN      1152
#define NC      10
#define CO      160
#define ROW     160           // halves per (b,n) row
#define TILE_N  32
#define SPLIT   6             // n-chunks per batch
#define CHUNK_T 6             // tiles per chunk (192 n)
#define CHUNK_N (TILE_N*CHUNK_T)
#define TILE_H  (TILE_N*ROW)  // 5120 halves = 10240 B per tile
#define POSE_OFF   0
#define ACT_OFF    40960
#define COUP_OFF   43520

// ---------------- cp.async helpers -----------------------------------------
__device__ __forceinline__ void cp_async16(void* smem_dst, const void* gsrc) {
    unsigned s = (unsigned)__cvta_generic_to_shared(smem_dst);
    asm volatile("cp.async.cg.shared.global [%0], [%1], 16;\n" :: "r"(s), "l"(gsrc));
}
__device__ __forceinline__ void cp_commit() {
    asm volatile("cp.async.commit_group;\n");
}
template <int N>
__device__ __forceinline__ void cp_wait() {
    asm volatile("cp.async.wait_group %0;\n" :: "n"(N));
}

// ============================================================================
// init: zero the atomic accumulators (must re-zero every graph replay)
// ============================================================================
__global__ void init_kernel() {
    int i = blockIdx.x * blockDim.x + threadIdx.x;
    if (i < 3 * NB * CO) ((float*)g_s)[i] = 0.f;
}

// ============================================================================
// Kernel A: votes[b,n,c,o] = sum_i W[n,c,o,i] * P[b,n,i]  (fp32 math, fp16 out)
// grid (1152, 8): (n, 32-b chunk). 160 threads: co4=t%40 owns 4 outputs.
// ============================================================================
__global__ __launch_bounds__(160) void votes_kernel(
    const float* __restrict__ P, const float* __restrict__ W)
{
    const int n    = blockIdx.x;
    const int bc   = blockIdx.y;
    const int t    = threadIdx.x;
    const int co4  = t % 40;
    const int bsub = t / 40;

    __shared__ float sp[32 * 16];
    for (int idx = t; idx < 512; idx += 160) {
        int bl = idx >> 4, i = idx & 15;
        sp[idx] = P[(size_t)(bc * 32 + bl) * (NN * 16) + (size_t)n * 16 + i];
    }

    float w[64];
    const float4* Wv = (const float4*)(W + ((size_t)n * CO + co4 * 4) * 16);
#pragma unroll
    for (int q = 0; q < 16; q++) {
        float4 x = Wv[q];
        w[q*4+0] = x.x; w[q*4+1] = x.y; w[q*4+2] = x.z; w[q*4+3] = x.w;
    }
    __syncthreads();

    for (int bl = bsub; bl < 32; bl += 4) {
        float p[16];
        const float4* pv = (const float4*)(sp + bl * 16);
#pragma unroll
        for (int j = 0; j < 4; j++) {
            float4 x = pv[j];
            p[j*4+0] = x.x; p[j*4+1] = x.y; p[j*4+2] = x.z; p[j*4+3] = x.w;
        }
        float a0 = 0.f, a1 = 0.f, a2 = 0.f, a3 = 0.f;
#pragma unroll
        for (int i = 0; i < 16; i++) {
            a0 = fmaf(w[i],      p[i], a0);
            a1 = fmaf(w[16 + i], p[i], a1);
            a2 = fmaf(w[32 + i], p[i], a2);
            a3 = fmaf(w[48 + i], p[i], a3);
        }
        union { __half2 h[2]; uint2 u; } pk;
        pk.h[0] = __floats2half2_rn(a0, a1);
        pk.h[1] = __floats2half2_rn(a2, a3);
        *(uint2*)(g_votes + ((size_t)(bc * 32 + bl) * NN + n) * ROW + co4 * 4) = pk.u;
    }
}

// ============================================================================
// Kernel B: one routing pass over a chunk of 192 n's. grid (256 b, 6 chunks),
// 512 threads = 32 n-slots x 16 c-lanes (c<10 active). Partial s -> atomicAdd.
// ============================================================================
template <int PASS>
__global__ __launch_bounds__(512, 2) void route_kernel(float* __restrict__ out)
{
    const int b     = blockIdx.x;
    const int chunk = blockIdx.y;
    const int t     = threadIdx.x;
    const int nl    = t >> 4;
    const int cl    = t & 15;

    // smem: 2 fp16 tiles (20480B) + svsum(640B) + ccs(2048B)
    __shared__ __align__(16) unsigned char smbuf[2 * TILE_H * 2 + 160 * 4 + 512 * 4];
    __half* tile0 = (__half*)smbuf;
    __half* tile1 = tile0 + TILE_H;
    float*  svsum = (float*)(smbuf + 2 * TILE_H * 2);
    float*  ccs   = svsum + 160;

    if (PASS > 0 && t < 160) svsum[t] = g_vsum[b * 160 + t];

    const __half* vb = g_votes + (size_t)b * (NN * ROW) + (size_t)chunk * (CHUNK_N * ROW);

    // prefetch tile 0 (640 x 16B)
#pragma unroll
    for (int i = 0; i < 2; i++) {
        int idx = t + i * 512;
        if (idx < TILE_H / 8) cp_async16(tile0 + idx * 8, vb + idx * 8);
    }
    cp_commit();

    float sacc[16];
#pragma unroll
    for (int o = 0; o < 16; o++) sacc[o] = 0.f;

    __syncthreads();   // svsum visible

    for (int k = 0; k < CHUNK_T; k++) {
        __half* cur = (k & 1) ? tile1 : tile0;
        __half* nxt = (k & 1) ? tile0 : tile1;
        if (k + 1 < CHUNK_T) {
            const __half* src = vb + (size_t)(k + 1) * TILE_H;
#pragma unroll
            for (int i = 0; i < 2; i++) {
                int idx = t + i * 512;
                if (idx < TILE_H / 8) cp_async16(nxt + idx * 8, src + idx * 8);
            }
            cp_commit();
            cp_wait<1>();
        } else {
            cp_wait<0>();
        }
        __syncthreads();

        // ---- load this (n,c)'s 16-vector ----
        float vv[16];
        if (cl < 10) {
            const uint4* rp = (const uint4*)(cur + nl * ROW + cl * 16);
#pragma unroll
            for (int j = 0; j < 2; j++) {
                uint4 q = rp[j];
                float2 f0 = __half22float2(*(__half2*)&q.x);
                float2 f1 = __half22float2(*(__half2*)&q.y);
                float2 f2 = __half22float2(*(__half2*)&q.z);
                float2 f3 = __half22float2(*(__half2*)&q.w);
                vv[j*8+0]=f0.x; vv[j*8+1]=f0.y; vv[j*8+2]=f1.x; vv[j*8+3]=f1.y;
                vv[j*8+4]=f2.x; vv[j*8+5]=f2.y; vv[j*8+6]=f3.x; vv[j*8+7]=f3.y;
            }
        } else {
#pragma unroll
            for (int o = 0; o < 16; o++) vv[o] = 0.f;
        }

        float cc;
        if (PASS == 0) {
            cc = 0.1f;
        } else {
            float lg;
            if (cl < 10) {
                lg = 0.f;
                const float4* sv = (const float4*)(svsum + cl * 16);
#pragma unroll
                for (int j = 0; j < 4; j++) {
                    float4 x = sv[j];
                    lg = fmaf(x.x, vv[j*4+0], lg);
                    lg = fmaf(x.y, vv[j*4+1], lg);
                    lg = fmaf(x.z, vv[j*4+2], lg);
                    lg = fmaf(x.w, vv[j*4+3], lg);
                }
            } else {
                lg = -1e30f;
            }
            float mx = lg;
#pragma unroll
            for (int m = 1; m < 16; m <<= 1)
                mx = fmaxf(mx, __shfl_xor_sync(0xFFFFFFFFu, mx, m, 16));
            float e = (cl < 10) ? __expf(lg - mx) : 0.f;
            float den = e;
#pragma unroll
            for (int m = 1; m < 16; m <<= 1)
                den += __shfl_xor_sync(0xFFFFFFFFu, den, m, 16);
            cc = e / den;
        }

#pragma unroll
        for (int o = 0; o < 16; o++) sacc[o] = fmaf(cc, vv[o], sacc[o]);

        if (PASS == 2) {
            if (cl < 10) ccs[nl * 16 + cl] = cc;
            __syncthreads();
            if (t < 320) {
                int c2 = t / 32, nn = t % 32;
                out[COUP_OFF + (size_t)b * (NC * NN) + (size_t)c2 * NN
                    + chunk * CHUNK_N + k * TILE_N + nn] = ccs[nn * 16 + c2];
            }
        }
        __syncthreads();
    }

    // ---- cross-slot reduction of s ----
    // warp holds 2 n-slots -> fold via shfl 16
#pragma unroll
    for (int o = 0; o < 16; o++)
        sacc[o] += __shfl_xor_sync(0xFFFFFFFFu, sacc[o], 16, 32);

    float* sred = (float*)smbuf;      // 16 warps * 256 floats = 16KB (tiles done)
    const int wid = t >> 5;
    if ((t & 16) == 0) {
#pragma unroll
        for (int j = 0; j < 4; j++) {
            float4 x = make_float4(sacc[j*4], sacc[j*4+1], sacc[j*4+2], sacc[j*4+3]);
            *(float4*)(sred + wid * 256 + cl * 16 + j * 4) = x;
        }
    }
    __syncthreads();

    if (t < 160) {
        float s = 0.f;
#pragma unroll
        for (int w2 = 0; w2 < 16; w2++) s += sred[w2 * 256 + t];
        atomicAdd(&g_s[PASS][b * 160 + t], s);
    }
}

// ============================================================================
// finish: bias + squash + vsum / final outputs. grid 256, 160 threads.
// ============================================================================
template <int PASS>
__global__ __launch_bounds__(160) void finish_kernel(
    const float* __restrict__ bias, float* __restrict__ out)
{
    const int b = blockIdx.x;
    const int t = threadIdx.x;
    const int c = t >> 4, o = t & 15;

    float s = g_s[PASS][b * 160 + t] + bias[t];

    float sq = s * s;
#pragma unroll
    for (int m = 1; m < 16; m <<= 1)
        sq += __shfl_xor_sync(0xFFFFFFFFu, sq, m, 16);

    float norm = sqrtf(sq + 1e-8f);
    float v = sq / (1.0f + sq) * (s / norm);

    if (PASS == 0) {
        g_vsum[b * 160 + t] = v;
    } else if (PASS == 1) {
        g_vsum[b * 160 + t] += v;
    } else {
        out[POSE_OFF + (size_t)b * 160 + t] = v;
        float vsq = v * v;
#pragma unroll
        for (int m = 1; m < 16; m <<= 1)
            vsq += __shfl_xor_sync(0xFFFFFFFFu, vsq, m, 16);
        if (o == 0) out[ACT_OFF + b * NC + c] = sqrtf(vsq + 1e-8f);
    }
}

// ============================================================================
extern "C" void kernel_launch(void* const* d_in, const int* in_sizes, int n_in,
                              void* d_out, int out_size)
{
    const float* P    = (const float*)d_in[0];  // (256,32,6,6,16,1)
    const float* W    = (const float*)d_in[2];  // (32,6,6,10,16,16)
    const float* bias = (const float*)d_in[3];  // (10,1,1,16,1)
    float* out = (float*)d_out;

    init_kernel<<<(3 * NB * CO + 511) / 512, 512>>>();
    votes_kernel<<<dim3(NN, 8), 160>>>(P, W);
    route_kernel<0><<<dim3(NB, SPLIT), 512>>>(out);
    finish_kernel<0><<<NB, 160>>>(bias, out);
    route_kernel<1><<<dim3(NB, SPLIT), 512>>>(out);
    finish_kernel<1><<<NB, 160>>>(bias, out);
    route_kernel<2><<<dim3(NB, SPLIT), 512>>>(out);
    finish_kernel<2><<<NB, 160>>>(bias, out);
}